// round 14
// baseline (speedup 1.0000x reference)
#include <cuda_runtime.h>
#include <cuda_fp16.h>
#include <math.h>
#include <stdint.h>

// Problem constants
static constexpr int NT  = 4096;
static constexpr int D   = 1024;
static constexpr int HD  = 4096;
static constexpr int NE  = 8;
static constexpr float CAPF = 4096.0f;
static constexpr float GEPS = 1e-6f;

// ---------------- device scratch ----------------
__device__ int   g_expert[NT];
__device__ float g_score[NT];
__device__ int   g_cnt[NE];
__device__ int   g_list[NE][NT];
__device__ float g_colsum[NE];
__device__ __half g_Xh[(size_t)NT * D];                      // x in fp16
__device__ __half g_H[(size_t)NT * HD];                      // hidden acts, fp16
__device__ uint32_t g_w1p[(size_t)NE * (D / 2) * HD];        // k-pair packed fp16
__device__ uint32_t g_w2p[(size_t)NE * (HD / 2) * D];
__device__ float g_part[(size_t)4 * NT * D];                 // GEMM2 K-split partials

// ---------------- helpers ----------------
__device__ __forceinline__ uint32_t smem_u32(const void* p) {
    uint32_t a;
    asm("{ .reg .u64 t; cvta.to.shared.u64 t, %1; cvt.u32.u64 %0, t; }" : "=r"(a) : "l"(p));
    return a;
}

__device__ __forceinline__ uint32_t pack_h2(float a, float b) {
    __half2 h = __floats2half2_rn(a, b);   // a -> low half
    return *reinterpret_cast<uint32_t*>(&h);
}

__device__ __forceinline__ void cpa16(uint32_t dst, const void* src, uint32_t srcsz) {
    asm volatile("cp.async.cg.shared.global [%0], [%1], 16, %2;"
                 :: "r"(dst), "l"(src), "r"(srcsz) : "memory");
}
__device__ __forceinline__ void cpa_commit() {
    asm volatile("cp.async.commit_group;" ::: "memory");
}
__device__ __forceinline__ void cpa_wait1() {
    asm volatile("cp.async.wait_group 1;" ::: "memory");
}

__device__ __forceinline__ void ldsm4(uint32_t* r, uint32_t a) {
    asm volatile("ldmatrix.sync.aligned.m8n8.x4.shared.b16 {%0,%1,%2,%3}, [%4];"
                 : "=r"(r[0]), "=r"(r[1]), "=r"(r[2]), "=r"(r[3]) : "r"(a));
}

__device__ __forceinline__ void mma16816f(float* c, const uint32_t* a, uint32_t b0, uint32_t b1) {
    asm volatile(
        "mma.sync.aligned.m16n8k16.row.col.f32.f16.f16.f32 "
        "{%0,%1,%2,%3}, {%4,%5,%6,%7}, {%8,%9}, {%0,%1,%2,%3};"
        : "+f"(c[0]), "+f"(c[1]), "+f"(c[2]), "+f"(c[3])
        : "r"(a[0]), "r"(a[1]), "r"(a[2]), "r"(a[3]), "r"(b0), "r"(b1));
}

// ---------------- small kernels (proven) ----------------
__global__ void init_kernel() {
    int t = threadIdx.x;
    if (t < NE) { g_cnt[t] = 0; g_colsum[t] = 0.0f; }
}

__global__ void gate_kernel(const float* __restrict__ x,
                            const float* __restrict__ wg,
                            const float* __restrict__ bg) {
    int tok  = (blockIdx.x * blockDim.x + threadIdx.x) >> 5;
    int lane = threadIdx.x & 31;
    if (tok >= NT) return;
    const float* xr = x + (size_t)tok * D;
    float acc[NE];
#pragma unroll
    for (int e = 0; e < NE; e++) acc[e] = 0.0f;
    for (int i = lane; i < D; i += 32) {
        float xv = xr[i];
        const float* wr = wg + (size_t)i * NE;
#pragma unroll
        for (int e = 0; e < NE; e++) acc[e] = fmaf(xv, wr[e], acc[e]);
    }
#pragma unroll
    for (int off = 16; off; off >>= 1)
#pragma unroll
        for (int e = 0; e < NE; e++)
            acc[e] += __shfl_xor_sync(0xffffffffu, acc[e], off);
    if (lane == 0) {
        float l[NE];
        l[0] = acc[0] + bg[0];
        float m = l[0]; int a = 0;
#pragma unroll
        for (int e = 1; e < NE; e++) {
            l[e] = acc[e] + bg[e];
            if (l[e] > m) { m = l[e]; a = e; }
        }
        float s = 0.0f;
#pragma unroll
        for (int e = 0; e < NE; e++) s += expf(l[e] - m);
        g_expert[tok] = a;
        g_score[tok]  = 1.0f / s;
        int pos = atomicAdd(&g_cnt[a], 1);
        g_list[a][pos] = tok;
    }
}

__global__ void colsum_kernel() {
    __shared__ float red[256];
    int e = blockIdx.x;
    float s = 0.0f;
    for (int n = threadIdx.x; n < NT; n += 256)
        if (g_expert[n] == e) s += g_score[n];
    red[threadIdx.x] = s;
    __syncthreads();
    for (int o = 128; o; o >>= 1) {
        if (threadIdx.x < o) red[threadIdx.x] += red[threadIdx.x + o];
        __syncthreads();
    }
    if (threadIdx.x == 0) g_colsum[e] = red[0];
}

__global__ void loss_kernel(float* __restrict__ out, int loss_idx) {
    if (threadIdx.x == 0 && blockIdx.x == 0) {
        float load[NE], tot = 0.0f;
#pragma unroll
        for (int e = 0; e < NE; e++) {
            float c = g_colsum[e];
            load[e] = c * CAPF / (c + GEPS);
            tot += load[e];
        }
        float imp = tot / (float)NT;
        float l = 0.0f;
#pragma unroll
        for (int e = 0; e < NE; e++) { float d = load[e] - imp; l += d * d; }
        out[loss_idx] = l / (float)NE;
    }
}

// x fp32 -> fp16 (layout preserved), 8 values/thread
__global__ void __launch_bounds__(256)
xsplit_kernel(const float* __restrict__ x, int n8) {
    int i = blockIdx.x * 256 + threadIdx.x;
    if (i >= n8) return;
    const float4* s = (const float4*)x + (size_t)i * 2;
    float4 v0 = s[0], v1 = s[1];
    uint4 w;
    w.x = pack_h2(v0.x, v0.y);
    w.y = pack_h2(v0.z, v0.w);
    w.z = pack_h2(v1.x, v1.y);
    w.w = pack_h2(v1.z, v1.w);
    ((uint4*)g_Xh)[i] = w;
}

// ---------------- weight pre-pack (proven) ----------------
template <int K, int N>
__global__ void __launch_bounds__(256)
prepack_kernel(const float* __restrict__ W, uint32_t* __restrict__ P) {
    int idx = blockIdx.x * 256 + threadIdx.x;
    constexpr int N8 = N / 8;
    if (idx >= NE * (K / 2) * N8) return;
    int n8 = idx % N8;
    int kp = (idx / N8) % (K / 2);
    int e  = idx / (N8 * (K / 2));
    const float* r0 = W + ((size_t)e * K + 2 * kp) * N + n8 * 8;
    const float* r1 = r0 + N;
    float4 a0 = *(const float4*)(r0);
    float4 a1 = *(const float4*)(r0 + 4);
    float4 b0 = *(const float4*)(r1);
    float4 b1 = *(const float4*)(r1 + 4);
    uint4 w0, w1;
    w0.x = pack_h2(a0.x, b0.x);
    w0.y = pack_h2(a0.y, b0.y);
    w0.z = pack_h2(a0.z, b0.z);
    w0.w = pack_h2(a0.w, b0.w);
    w1.x = pack_h2(a1.x, b1.x);
    w1.y = pack_h2(a1.y, b1.y);
    w1.z = pack_h2(a1.z, b1.z);
    w1.w = pack_h2(a1.w, b1.w);
    uint32_t* dst = P + ((size_t)e * (K / 2) + kp) * N + n8 * 8;
    *(uint4*)(dst)     = w0;
    *(uint4*)(dst + 4) = w1;
}

// ---------------- fp16 tensor GEMM, cp.async 3-stage, BK=64 ----------------
// CTA 128m x 128n, BK=64, 8 warps (2m x 4n), 2 CTAs/SM.
// A via ldmatrix.x4; B via scalar LDS; both layouts proven (extended k-range).
static constexpr int AST = 36;                   // A row stride, words (64 halfs + pad)
static constexpr int BST = 136;                  // B kpair-row stride, words
static constexpr int AS_W = 128 * AST;           // 4608 words / stage
static constexpr int BS_W = 32 * BST;            // 4352 words / stage
static constexpr int SMEM_BYTES = 3 * (AS_W + BS_W) * 4;   // 107520

template <int KSTRIDE, int KLEN, int NDIM, bool GELU, int NSPLIT>
__global__ void __launch_bounds__(256, 2)
ffn_fp16(const float* __restrict__ bias,  // [NE][NDIM]
         float* __restrict__ out) {
    extern __shared__ uint32_t dyn[];
    uint32_t* AsBase = dyn;               // [3][AS_W]
    uint32_t* BsBase = dyn + 3 * AS_W;    // [3][BS_W]
    __shared__ int   toks[128];
    __shared__ float gw[128];

    int e = blockIdx.z / NSPLIT;
    int split = blockIdx.z % NSPLIT;
    int cnt = g_cnt[e];
    int mstart = blockIdx.y * 128;
    if (mstart >= cnt) return;
    int n0 = blockIdx.x * 128;

    int tid = threadIdx.x;
    int wid = tid >> 5, lane = tid & 31;

    if (tid < 128) {
        int rr = mstart + tid;
        int tok = (rr < cnt) ? g_list[e][rr] : -1;
        toks[tid] = tok;
        if (!GELU && NSPLIT == 1) {
            float g = 0.0f;
            if (tok >= 0) g = g_score[tok] * CAPF / (g_colsum[e] + GEPS);
            gw[tid] = g;
        }
    }
    __syncthreads();

    uint32_t asb = smem_u32(AsBase);
    uint32_t bsb = smem_u32(BsBase);

    // ---- cp.async assignments (BK=64) ----
    // A tile: 128 rows x 128B. thread t -> row r=t>>1, 64B half h=t&1; 4x16B per iter
    int ar = tid >> 1;
    int atok = toks[ar];
    size_t arow = (size_t)(atok >= 0 ? atok : 0);
    const __half* aGlob = GELU ? g_Xh : g_H;
    const char* aSrc = (const char*)(aGlob + arow * KSTRIDE + split * KLEN) + (tid & 1) * 64;
    uint32_t a_dst = (uint32_t)(ar * (AST * 4) + (tid & 1) * 64);
    uint32_t asz = (atok >= 0) ? 16u : 0u;

    // B tile: 32 kpair rows x 512B. thread t -> row kp=t>>3, 64B chunk c=t&7; 4x16B
    const uint32_t* Wp = GELU ? g_w1p : g_w2p;
    const char* bSrc = (const char*)(Wp + ((size_t)e * (KSTRIDE / 2) + split * (KLEN / 2)
                                           + (tid >> 3)) * NDIM + n0 + (tid & 7) * 16);
    uint32_t b_dst = (uint32_t)((tid >> 3) * (BST * 4) + (tid & 7) * 64);

    auto issue = [&](int it) {
        uint32_t s = (uint32_t)(it % 3);
        uint32_t ad = asb + s * (AS_W * 4) + a_dst;
        const char* ap = aSrc + (size_t)it * 128;          // 64 halfs per iter
#pragma unroll
        for (int j = 0; j < 4; j++) cpa16(ad + j * 16, ap + j * 16, asz);
        uint32_t bd = bsb + s * (BS_W * 4) + b_dst;
        const char* bq = bSrc + (size_t)it * 32 * NDIM * 4; // 32 kpair rows per iter
#pragma unroll
        for (int j = 0; j < 4; j++) cpa16(bd + j * 16, bq + j * 16, 16u);
        cpa_commit();
    };

    // warp tile coords
    int wm = (wid & 1) * 64;
    int wn = (wid >> 1) * 32;
    int gid = lane >> 2, tig = lane & 3;
    uint32_t a_ld = (uint32_t)(((wm + (lane & 15)) * AST + (lane >> 4) * 4) * 4);

    float acc[4][4][4];
#pragma unroll
    for (int mb = 0; mb < 4; mb++)
#pragma unroll
        for (int nb = 0; nb < 4; nb++)
#pragma unroll
            for (int q = 0; q < 4; q++) acc[mb][nb][q] = 0.0f;

    constexpr int NIT = KLEN / 64;

    issue(0);
    issue(1);

    for (int it = 0; it < NIT; it++) {
        cpa_wait1();          // stage it%3 landed (groups 0..it complete)
        __syncthreads();
        if (it + 2 < NIT) issue(it + 2);
        else cpa_commit();    // keep group numbering aligned

        uint32_t sA = asb + (uint32_t)(it % 3) * (AS_W * 4);
        const uint32_t* BsS = BsBase + (it % 3) * BS_W;

#pragma unroll
        for (int ks = 0; ks < 4; ks++) {
            uint32_t ah[4][4];
#pragma unroll
            for (int mb = 0; mb < 4; mb++)
                ldsm4(ah[mb], sA + a_ld + (uint32_t)((mb * 16 * AST + ks * 8) * 4));
            uint32_t bh[4][2];
#pragma unroll
            for (int nb = 0; nb < 4; nb++) {
                int base = (ks * 8 + tig) * BST + wn + nb * 8 + gid;
                bh[nb][0] = BsS[base];
                bh[nb][1] = BsS[base + 4 * BST];
            }
#pragma unroll
            for (int mb = 0; mb < 4; mb++)
#pragma unroll
                for (int nb = 0; nb < 4; nb++)
                    mma16816f(acc[mb][nb], ah[mb], bh[nb][0], bh[nb][1]);
        }
    }

    // ---- epilogue ----
    const float* be = bias + (size_t)e * NDIM + n0;
#pragma unroll
    for (int mb = 0; mb < 4; mb++) {
#pragma unroll
        for (int half = 0; half < 2; half++) {
            int rm = wm + mb * 16 + gid + half * 8;
            int tok = toks[rm];
            if (tok < 0) continue;
#pragma unroll
            for (int nb = 0; nb < 4; nb++) {
                int cn = wn + nb * 8 + 2 * tig;
                float a0 = acc[mb][nb][half * 2 + 0];
                float a1 = acc[mb][nb][half * 2 + 1];
                if (GELU) {
                    float v0 = a0 + __ldg(be + cn);
                    float v1 = a1 + __ldg(be + cn + 1);
                    v0 = v0 / (1.0f + expf(-1.702f * v0));
                    v1 = v1 / (1.0f + expf(-1.702f * v1));
                    size_t o = ((size_t)tok * NDIM + n0 + cn) >> 1;
                    ((uint32_t*)g_H)[o] = pack_h2(v0, v1);
                } else if (NSPLIT > 1) {
                    *(float2*)(g_part + ((size_t)split * NT + tok) * NDIM + n0 + cn) =
                        make_float2(a0, a1);
                } else {
                    float g = gw[rm];
                    float v0 = a0 + __ldg(be + cn);
                    float v1 = a1 + __ldg(be + cn + 1);
                    *(float2*)(out + (size_t)tok * NDIM + n0 + cn) =
                        make_float2(v0 * g, v1 * g);
                }
            }
        }
    }
}

// ---------------- deterministic K-split reduce + bias + gate ----------------
__global__ void __launch_bounds__(256)
reduce_kernel(const float* __restrict__ b2, float* __restrict__ out) {
    int tok = blockIdx.x;
    int c = threadIdx.x * 4;
    int e = g_expert[tok];
    float g = g_score[tok] * CAPF / (g_colsum[e] + GEPS);
    size_t off = (size_t)tok * D + c;
    float4 s0 = *(const float4*)(g_part + 0 * (size_t)NT * D + off);
    float4 s1 = *(const float4*)(g_part + 1 * (size_t)NT * D + off);
    float4 s2 = *(const float4*)(g_part + 2 * (size_t)NT * D + off);
    float4 s3 = *(const float4*)(g_part + 3 * (size_t)NT * D + off);
    float4 bb = *(const float4*)(b2 + (size_t)e * D + c);
    float4 r;
    r.x = (((s0.x + s1.x) + s2.x) + s3.x + bb.x) * g;
    r.y = (((s0.y + s1.y) + s2.y) + s3.y + bb.y) * g;
    r.z = (((s0.z + s1.z) + s2.z) + s3.z + bb.z) * g;
    r.w = (((s0.w + s1.w) + s2.w) + s3.w + bb.w) * g;
    *(float4*)(out + off) = r;
}

// ---------------- launch ----------------
extern "C" void kernel_launch(void* const* d_in, const int* in_sizes, int n_in,
                              void* d_out, int out_size) {
    const float* x  = (const float*)d_in[0];
    const float* wg = (const float*)d_in[1];
    const float* bg = (const float*)d_in[2];
    const float* w1 = (const float*)d_in[3];
    const float* b1 = (const float*)d_in[4];
    const float* w2 = (const float*)d_in[5];
    const float* b2 = (const float*)d_in[6];
    float* out = (float*)d_out;

    uint32_t *w1p, *w2p;
    cudaGetSymbolAddress((void**)&w1p, g_w1p);
    cudaGetSymbolAddress((void**)&w2p, g_w2p);

    cudaFuncSetAttribute(ffn_fp16<D, D, HD, true, 1>,
                         cudaFuncAttributeMaxDynamicSharedMemorySize, SMEM_BYTES);
    cudaFuncSetAttribute(ffn_fp16<HD, HD / 4, D, false, 4>,
                         cudaFuncAttributeMaxDynamicSharedMemorySize, SMEM_BYTES);

    init_kernel<<<1, 32>>>();
    gate_kernel<<<(NT * 32 + 255) / 256, 256>>>(x, wg, bg);
    colsum_kernel<<<NE, 256>>>();
    loss_kernel<<<1, 32>>>(out, out_size - 1);

    xsplit_kernel<<<(NT * D / 8 + 255) / 256, 256>>>(x, NT * D / 8);
    {
        int n1 = NE * (D / 2) * (HD / 8);
        prepack_kernel<D, HD><<<(n1 + 255) / 256, 256>>>(w1, w1p);
        int n2 = NE * (HD / 2) * (D / 8);
        prepack_kernel<HD, D><<<(n2 + 255) / 256, 256>>>(w2, w2p);
    }

    // GEMM1: H = gelu(x @ w1 + b1) -> g_H (fp16)
    ffn_fp16<D, D, HD, true, 1>
        <<<dim3(HD / 128, NT / 128, NE), 256, SMEM_BYTES>>>(b1, nullptr);
    // GEMM2 (K-split x4): partials to g_part
    ffn_fp16<HD, HD / 4, D, false, 4>
        <<<dim3(D / 128, NT / 128, NE * 4), 256, SMEM_BYTES>>>(b2, nullptr);
    // reduce: out = (sum parts + b2) * gate
    reduce_kernel<<<NT, 256>>>(b2, out);
}

// round 17
// speedup vs baseline: 1.1050x; 1.1050x over previous
#include <cuda_runtime.h>
#include <cuda_fp16.h>
#include <math.h>
#include <stdint.h>

// Problem constants
static constexpr int NT  = 4096;
static constexpr int D   = 1024;
static constexpr int HD  = 4096;
static constexpr int NE  = 8;
static constexpr float CAPF = 4096.0f;
static constexpr float GEPS = 1e-6f;

// ---------------- device scratch ----------------
__device__ int   g_expert[NT];
__device__ float g_score[NT];
__device__ int   g_cnt[NE];
__device__ int   g_list[NE][NT];
__device__ float g_colsum[NE];
__device__ __half g_Xh[(size_t)NT * D];                      // x in fp16
__device__ __half g_H[(size_t)NT * HD];                      // hidden acts, fp16
__device__ uint32_t g_w1p[(size_t)NE * (D / 2) * HD];        // k-pair packed fp16
__device__ uint32_t g_w2p[(size_t)NE * (HD / 2) * D];
__device__ float g_part[(size_t)4 * NT * D];                 // GEMM2 K-split partials

// ---------------- helpers ----------------
__device__ __forceinline__ uint32_t smem_u32(const void* p) {
    uint32_t a;
    asm("{ .reg .u64 t; cvta.to.shared.u64 t, %1; cvt.u32.u64 %0, t; }" : "=r"(a) : "l"(p));
    return a;
}

__device__ __forceinline__ uint32_t pack_h2(float a, float b) {
    __half2 h = __floats2half2_rn(a, b);   // a -> low half
    return *reinterpret_cast<uint32_t*>(&h);
}

__device__ __forceinline__ void cpa16(uint32_t dst, const void* src, uint32_t srcsz) {
    asm volatile("cp.async.cg.shared.global [%0], [%1], 16, %2;"
                 :: "r"(dst), "l"(src), "r"(srcsz) : "memory");
}
__device__ __forceinline__ void cpa_commit() {
    asm volatile("cp.async.commit_group;" ::: "memory");
}
__device__ __forceinline__ void cpa_wait1() {
    asm volatile("cp.async.wait_group 1;" ::: "memory");
}

__device__ __forceinline__ void ldsm4(uint32_t* r, uint32_t a) {
    asm volatile("ldmatrix.sync.aligned.m8n8.x4.shared.b16 {%0,%1,%2,%3}, [%4];"
                 : "=r"(r[0]), "=r"(r[1]), "=r"(r[2]), "=r"(r[3]) : "r"(a));
}

__device__ __forceinline__ void mma16816f(float* c, const uint32_t* a, uint32_t b0, uint32_t b1) {
    asm volatile(
        "mma.sync.aligned.m16n8k16.row.col.f32.f16.f16.f32 "
        "{%0,%1,%2,%3}, {%4,%5,%6,%7}, {%8,%9}, {%0,%1,%2,%3};"
        : "+f"(c[0]), "+f"(c[1]), "+f"(c[2]), "+f"(c[3])
        : "r"(a[0]), "r"(a[1]), "r"(a[2]), "r"(a[3]), "r"(b0), "r"(b1));
}

// ---------------- small kernels (proven) ----------------
__global__ void gate_kernel(const float* __restrict__ x,
                            const float* __restrict__ wg,
                            const float* __restrict__ bg) {
    int tok  = (blockIdx.x * blockDim.x + threadIdx.x) >> 5;
    int lane = threadIdx.x & 31;
    if (tok >= NT) return;
    const float* xr = x + (size_t)tok * D;
    float acc[NE];
#pragma unroll
    for (int e = 0; e < NE; e++) acc[e] = 0.0f;
    for (int i = lane; i < D; i += 32) {
        float xv = xr[i];
        const float* wr = wg + (size_t)i * NE;
#pragma unroll
        for (int e = 0; e < NE; e++) acc[e] = fmaf(xv, wr[e], acc[e]);
    }
#pragma unroll
    for (int off = 16; off; off >>= 1)
#pragma unroll
        for (int e = 0; e < NE; e++)
            acc[e] += __shfl_xor_sync(0xffffffffu, acc[e], off);
    if (lane == 0) {
        float l[NE];
        l[0] = acc[0] + bg[0];
        float m = l[0]; int a = 0;
#pragma unroll
        for (int e = 1; e < NE; e++) {
            l[e] = acc[e] + bg[e];
            if (l[e] > m) { m = l[e]; a = e; }
        }
        float s = 0.0f;
#pragma unroll
        for (int e = 0; e < NE; e++) s += expf(l[e] - m);
        g_expert[tok] = a;
        g_score[tok]  = 1.0f / s;
        int pos = atomicAdd(&g_cnt[a], 1);
        g_list[a][pos] = tok;
    }
}

__global__ void colsum_kernel() {
    __shared__ float red[256];
    int e = blockIdx.x;
    float s = 0.0f;
    for (int n = threadIdx.x; n < NT; n += 256)
        if (g_expert[n] == e) s += g_score[n];
    red[threadIdx.x] = s;
    __syncthreads();
    for (int o = 128; o; o >>= 1) {
        if (threadIdx.x < o) red[threadIdx.x] += red[threadIdx.x + o];
        __syncthreads();
    }
    if (threadIdx.x == 0) g_colsum[e] = red[0];
}

__global__ void loss_kernel(float* __restrict__ out, int loss_idx) {
    if (threadIdx.x == 0 && blockIdx.x == 0) {
        float load[NE], tot = 0.0f;
#pragma unroll
        for (int e = 0; e < NE; e++) {
            float c = g_colsum[e];
            load[e] = c * CAPF / (c + GEPS);
            tot += load[e];
        }
        float imp = tot / (float)NT;
        float l = 0.0f;
#pragma unroll
        for (int e = 0; e < NE; e++) { float d = load[e] - imp; l += d * d; }
        out[loss_idx] = l / (float)NE;
    }
}

// ---------------- fused pre-pass: init + xsplit + prepack(w1) + prepack(w2) ----------------
// Per-item work identical to the separate R13 kernels (bitwise-same outputs).
__device__ __forceinline__ void prepack_item(const float* __restrict__ W,
                                             uint32_t* __restrict__ P,
                                             int idx, int K, int N) {
    int N8 = N / 8;
    int n8 = idx % N8;
    int kp = (idx / N8) % (K / 2);
    int e  = idx / (N8 * (K / 2));
    const float* r0 = W + ((size_t)e * K + 2 * kp) * N + n8 * 8;
    const float* r1 = r0 + N;
    float4 a0 = *(const float4*)(r0);
    float4 a1 = *(const float4*)(r0 + 4);
    float4 b0 = *(const float4*)(r1);
    float4 b1 = *(const float4*)(r1 + 4);
    uint4 w0, w1;
    w0.x = pack_h2(a0.x, b0.x);
    w0.y = pack_h2(a0.y, b0.y);
    w0.z = pack_h2(a0.z, b0.z);
    w0.w = pack_h2(a0.w, b0.w);
    w1.x = pack_h2(a1.x, b1.x);
    w1.y = pack_h2(a1.y, b1.y);
    w1.z = pack_h2(a1.z, b1.z);
    w1.w = pack_h2(a1.w, b1.w);
    uint32_t* dst = P + ((size_t)e * (K / 2) + kp) * N + n8 * 8;
    *(uint4*)(dst)     = w0;
    *(uint4*)(dst + 4) = w1;
}

static constexpr int NX_ITEMS  = NT * D / 8;                 // 524288
static constexpr int NP1_ITEMS = NE * (D / 2) * (HD / 8);    // 2097152
static constexpr int NP2_ITEMS = NE * (HD / 2) * (D / 8);    // 2097152
static constexpr int PRE_ITEMS = NX_ITEMS + NP1_ITEMS + NP2_ITEMS;

__global__ void __launch_bounds__(256)
fused_pre_kernel(const float* __restrict__ x,
                 const float* __restrict__ w1,
                 const float* __restrict__ w2,
                 uint32_t* __restrict__ w1p,
                 uint32_t* __restrict__ w2p) {
    int idx = blockIdx.x * 256 + threadIdx.x;
    if (idx < NE) { g_cnt[idx] = 0; g_colsum[idx] = 0.0f; }
    if (idx < NX_ITEMS) {
        const float4* s = (const float4*)x + (size_t)idx * 2;
        float4 v0 = s[0], v1 = s[1];
        uint4 w;
        w.x = pack_h2(v0.x, v0.y);
        w.y = pack_h2(v0.z, v0.w);
        w.z = pack_h2(v1.x, v1.y);
        w.w = pack_h2(v1.z, v1.w);
        ((uint4*)g_Xh)[idx] = w;
    } else if (idx < NX_ITEMS + NP1_ITEMS) {
        prepack_item(w1, w1p, idx - NX_ITEMS, D, HD);
    } else if (idx < PRE_ITEMS) {
        prepack_item(w2, w2p, idx - NX_ITEMS - NP1_ITEMS, HD, D);
    }
}

// ---------------- fp16 tensor GEMM, cp.async 3-stage (R13 exact) ----------------
// CTA 128m x 128n, BK=32, 8 warps (2m x 4n), 2 CTAs/SM.
// A via ldmatrix.x4; B via scalar LDS.
static constexpr int AST = 20;                   // A row stride, words
static constexpr int BST = 136;                  // B row stride, words
static constexpr int AS_W = 128 * AST;           // 2560 words / stage
static constexpr int BS_W = 16 * BST;            // 2176 words / stage
static constexpr int SMEM_BYTES = 3 * (AS_W + BS_W) * 4;   // 56832

template <int KSTRIDE, int KLEN, int NDIM, bool GELU, int NSPLIT>
__global__ void __launch_bounds__(256, 2)
ffn_fp16(const float* __restrict__ bias,  // [NE][NDIM]
         float* __restrict__ out) {
    extern __shared__ uint32_t dyn[];
    uint32_t* AsBase = dyn;               // [3][AS_W]
    uint32_t* BsBase = dyn + 3 * AS_W;    // [3][BS_W]
    __shared__ int   toks[128];
    __shared__ float gw[128];

    int e = blockIdx.z / NSPLIT;
    int split = blockIdx.z % NSPLIT;
    int cnt = g_cnt[e];
    int mstart = blockIdx.y * 128;
    if (mstart >= cnt) return;
    int n0 = blockIdx.x * 128;

    int tid = threadIdx.x;
    int wid = tid >> 5, lane = tid & 31;

    if (tid < 128) {
        int rr = mstart + tid;
        int tok = (rr < cnt) ? g_list[e][rr] : -1;
        toks[tid] = tok;
        if (!GELU && NSPLIT == 1) {
            float g = 0.0f;
            if (tok >= 0) g = g_score[tok] * CAPF / (g_colsum[e] + GEPS);
            gw[tid] = g;
        }
    }
    __syncthreads();

    uint32_t asb = smem_u32(AsBase);
    uint32_t bsb = smem_u32(BsBase);

    // ---- cp.async assignments ----
    // A: thread t -> row r=t>>1, 32B half h=t&1; 2x16B per iter
    int ar = tid >> 1;
    int atok = toks[ar];
    size_t arow = (size_t)(atok >= 0 ? atok : 0);
    const __half* aGlob = GELU ? g_Xh : g_H;
    const char* aSrc = (const char*)(aGlob + arow * KSTRIDE + split * KLEN) + (tid & 1) * 32;
    uint32_t a_dst = (uint32_t)(ar * 80 + (tid & 1) * 32);
    uint32_t asz = (atok >= 0) ? 16u : 0u;

    // B: thread t -> kpair kp=t>>4, 32B chunk (t&15); 2x16B per iter
    const uint32_t* Wp = GELU ? g_w1p : g_w2p;
    const char* bSrc = (const char*)(Wp + ((size_t)e * (KSTRIDE / 2) + split * (KLEN / 2)
                                           + (tid >> 4)) * NDIM + n0 + (tid & 15) * 8);
    uint32_t b_dst = (uint32_t)((tid >> 4) * 544 + (tid & 15) * 32);

    auto issue = [&](int it) {
        uint32_t s = (uint32_t)(it % 3);
        uint32_t ad = asb + s * (AS_W * 4) + a_dst;
        const char* ap = aSrc + (size_t)it * 64;          // 32 halfs per iter
        cpa16(ad, ap, asz);
        cpa16(ad + 16, ap + 16, asz);
        uint32_t bd = bsb + s * (BS_W * 4) + b_dst;
        const char* bq = bSrc + (size_t)it * 16 * NDIM * 4; // 16 kpair rows per iter
        cpa16(bd, bq, 16u);
        cpa16(bd + 16, bq + 16, 16u);
        cpa_commit();
    };

    // warp tile coords
    int wm = (wid & 1) * 64;
    int wn = (wid >> 1) * 32;
    int gid = lane >> 2, tig = lane & 3;
    uint32_t a_ld = (uint32_t)(((wm + (lane & 15)) * AST + (lane >> 4) * 4) * 4);

    float acc[4][4][4];
#pragma unroll
    for (int mb = 0; mb < 4; mb++)
#pragma unroll
        for (int nb = 0; nb < 4; nb++)
#pragma unroll
            for (int q = 0; q < 4; q++) acc[mb][nb][q] = 0.0f;

    constexpr int NIT = KLEN / 32;

    issue(0);
    issue(1);

    for (int it = 0; it < NIT; it++) {
        cpa_wait1();          // stage it%3 landed (groups 0..it complete)
        __syncthreads();
        if (it + 2 < NIT) issue(it + 2);
        else cpa_commit();    // keep group numbering aligned

        uint32_t sA = asb + (uint32_t)(it % 3) * (AS_W * 4);
        const uint32_t* BsS = BsBase + (it % 3) * BS_W;

#pragma unroll
        for (int ks = 0; ks < 2; ks++) {
            uint32_t ah[4][4];
#pragma unroll
            for (int mb = 0; mb < 4; mb++)
                ldsm4(ah[mb], sA + a_ld + (uint32_t)((mb * 16 * AST + ks * 8) * 4));
            uint32_t bh[4][2];
#pragma unroll
            for (int nb = 0; nb < 4; nb++) {
                int base = (ks * 8 + tig) * BST + wn + nb * 8 + gid;
                bh[nb][0] = BsS[base];
                bh[nb][1] = BsS[base + 4 * BST];
            }
#pragma unroll
            for (int mb = 0; mb < 4; mb++)
#pragma unroll
                for (int nb = 0; nb < 4; nb++)
                    mma16816f(acc[mb][nb], ah[mb], bh[nb][0], bh[nb][1]);
        }
    }

    // ---- epilogue ----
    const float* be = bias + (size_t)e * NDIM + n0;
#pragma unroll
    for (int mb = 0; mb < 4; mb++) {
#pragma unroll
        for (int half = 0; half < 2; half++) {
            int rm = wm + mb * 16 + gid + half * 8;
            int tok = toks[rm];
            if (tok < 0) continue;
#pragma unroll
            for (int nb = 0; nb < 4; nb++) {
                int cn = wn + nb * 8 + 2 * tig;
                float a0 = acc[mb][nb][half * 2 + 0];
                float a1 = acc[mb][nb][half * 2 + 1];
                if (GELU) {
                    float v0 = a0 + __ldg(be + cn);
                    float v1 = a1 + __ldg(be + cn + 1);
                    v0 = v0 / (1.0f + expf(-1.702f * v0));
                    v1 = v1 / (1.0f + expf(-1.702f * v1));
                    size_t o = ((size_t)tok * NDIM + n0 + cn) >> 1;
                    ((uint32_t*)g_H)[o] = pack_h2(v0, v1);
                } else if (NSPLIT > 1) {
                    *(float2*)(g_part + ((size_t)split * NT + tok) * NDIM + n0 + cn) =
                        make_float2(a0, a1);
                } else {
                    float g = gw[rm];
                    float v0 = a0 + __ldg(be + cn);
                    float v1 = a1 + __ldg(be + cn + 1);
                    *(float2*)(out + (size_t)tok * NDIM + n0 + cn) =
                        make_float2(v0 * g, v1 * g);
                }
            }
        }
    }
}

// ---------------- deterministic K-split reduce + bias + gate ----------------
__global__ void __launch_bounds__(256)
reduce_kernel(const float* __restrict__ b2, float* __restrict__ out) {
    int tok = blockIdx.x;
    int c = threadIdx.x * 4;
    int e = g_expert[tok];
    float g = g_score[tok] * CAPF / (g_colsum[e] + GEPS);
    size_t off = (size_t)tok * D + c;
    float4 s0 = *(const float4*)(g_part + 0 * (size_t)NT * D + off);
    float4 s1 = *(const float4*)(g_part + 1 * (size_t)NT * D + off);
    float4 s2 = *(const float4*)(g_part + 2 * (size_t)NT * D + off);
    float4 s3 = *(const float4*)(g_part + 3 * (size_t)NT * D + off);
    float4 bb = *(const float4*)(b2 + (size_t)e * D + c);
    float4 r;
    r.x = (((s0.x + s1.x) + s2.x) + s3.x + bb.x) * g;
    r.y = (((s0.y + s1.y) + s2.y) + s3.y + bb.y) * g;
    r.z = (((s0.z + s1.z) + s2.z) + s3.z + bb.z) * g;
    r.w = (((s0.w + s1.w) + s2.w) + s3.w + bb.w) * g;
    *(float4*)(out + off) = r;
}

// ---------------- launch ----------------
extern "C" void kernel_launch(void* const* d_in, const int* in_sizes, int n_in,
                              void* d_out, int out_size) {
    const float* x  = (const float*)d_in[0];
    const float* wg = (const float*)d_in[1];
    const float* bg = (const float*)d_in[2];
    const float* w1 = (const float*)d_in[3];
    const float* b1 = (const float*)d_in[4];
    const float* w2 = (const float*)d_in[5];
    const float* b2 = (const float*)d_in[6];
    float* out = (float*)d_out;

    uint32_t *w1p, *w2p;
    cudaGetSymbolAddress((void**)&w1p, g_w1p);
    cudaGetSymbolAddress((void**)&w2p, g_w2p);

    cudaFuncSetAttribute(ffn_fp16<D, D, HD, true, 1>,
                         cudaFuncAttributeMaxDynamicSharedMemorySize, SMEM_BYTES);
    cudaFuncSetAttribute(ffn_fp16<HD, HD / 4, D, false, 4>,
                         cudaFuncAttributeMaxDynamicSharedMemorySize, SMEM_BYTES);

    // fused: init counters + x->fp16 + both weight prepacks (one launch)
    fused_pre_kernel<<<(PRE_ITEMS + 255) / 256, 256>>>(x, w1, w2, w1p, w2p);

    gate_kernel<<<(NT * 32 + 255) / 256, 256>>>(x, wg, bg);
    colsum_kernel<<<NE, 256>>>();
    loss_kernel<<<1, 32>>>(out, out_size - 1);

    // GEMM1: H = gelu(x @ w1 + b1) -> g_H (fp16)
    ffn_fp16<D, D, HD, true, 1>
        <<<dim3(HD / 128, NT / 128, NE), 256, SMEM_BYTES>>>(b1, nullptr);
    // GEMM2 (K-split x4): partials to g_part
    ffn_fp16<HD, HD / 4, D, false, 4>
        <<<dim3(D / 128, NT / 128, NE * 4), 256, SMEM_BYTES>>>(b2, nullptr);
    // reduce: out = (sum parts + b2) * gate
    reduce_kernel<<<NT, 256>>>(b2, out);
}